// round 3
// baseline (speedup 1.0000x reference)
#include <cuda_runtime.h>
#include <math.h>

// ---------------- problem constants ----------------
#define N_TOT   65536      // B*H*W
#define K_CB    512
#define KH      256        // codes per half
#define C_DIM   64
#define B_DIM   64
#define HW      1024

#define TM      64         // rows per tile
#define ATHREADS 256
#define WROW2   258        // wTh row stride (floats): even (8B LDS.64 align), bank stride 2

// output layout (floats), concatenation of the reference tuple
#define Q_OFF     0ULL                       // [64,64,32,32] = 4194304
#define LOSS_OFF  4194304ULL                 // [64]
#define PERP_OFF  4194368ULL                 // [1]
#define ENC_OFF   4194369ULL                 // [65536,512] = 33554432
#define EIDX_OFF  37748801ULL                // [64,1024]   = 65536
#define DIST_OFF  37814337ULL                // [65536,512] = 33554432
#define OUT_TOTAL 71368769

// kernel A smem layout (floats)
#define SM_WT   0
#define SM_XSD  (64*WROW2)             // xsd[c][r] duplicated pairs: 64*64*2 floats
#define SM_WN   (SM_XSD + 64*64*2)     // wnorm[256]
#define SM_XN   (SM_WN + 256)          // xnorm[64]
#define SM_TOTF (SM_XN + 64)
#define SMEM_A  (SM_TOTF*4)            // ~100 KB -> 2 CTAs/SM

__device__ float g_cbest[2 * N_TOT];
__device__ int   g_cidx [2 * N_TOT];
__device__ float g_lpart[1024];
__device__ int   g_hist [K_CB];        // zero at module load; finish kernel re-zeroes

// ---------------- f32x2 helpers ----------------
__device__ __forceinline__ void fma2(unsigned long long &d, unsigned long long a, unsigned long long b) {
    asm("fma.rn.f32x2 %0, %1, %2, %3;" : "=l"(d) : "l"(a), "l"(b), "l"(d));
}
__device__ __forceinline__ void unpack2(unsigned long long v, float &lo, float &hi) {
    asm("mov.b64 {%0, %1}, %2;" : "=f"(lo), "=f"(hi) : "l"(v));
}

// ---------------- kernel A: half-codebook distances + per-half argmin ----------------
extern "C" __global__ void __launch_bounds__(ATHREADS, 2)
vq_dist(const float* __restrict__ inputs, const float* __restrict__ weight,
        float* __restrict__ out)
{
    extern __shared__ float smem[];
    float* wTh   = smem + SM_WT;     // wTh[c][k_local], row stride WROW2
    float* xsd   = smem + SM_XSD;    // duplicated pairs {x,x} per (c, r)
    float* wnorm = smem + SM_WN;
    float* xnorm = smem + SM_XN;

    const int tid   = threadIdx.x;
    const int ntile = blockIdx.x >> 1;
    const int half  = blockIdx.x & 1;
    const int n0    = ntile * TM;           // 64-aligned -> single batch image
    const int b     = n0 >> 10;
    const int p0    = n0 & (HW - 1);

    // load this half of the codebook [KH,C] -> transposed smem (float4 gmem reads)
    {
        const float4* w4 = (const float4*)(weight + (size_t)half * KH * C_DIM);
        for (int i = tid; i < KH * C_DIM / 4; i += ATHREADS) {
            int k = i >> 4, c0 = (i & 15) * 4;
            float4 v = w4[i];
            wTh[(c0    ) * WROW2 + k] = v.x;
            wTh[(c0 + 1) * WROW2 + k] = v.y;
            wTh[(c0 + 2) * WROW2 + k] = v.z;
            wTh[(c0 + 3) * WROW2 + k] = v.w;
        }
    }
    // load x tile, duplicated: xsd pair index (c*64 + r)
    const float* xbase = inputs + (size_t)b * (C_DIM * HW) + p0;
    for (int i = tid; i < C_DIM * TM; i += ATHREADS) {
        int c = i >> 6, r = i & 63;
        float v = xbase[(size_t)c * HW + r];
        ((float2*)xsd)[c * 64 + r] = make_float2(v, v);
    }
    __syncthreads();

    // wnorm[k] = sum_c wTh[c][k]^2 ; xnorm[r] = sum_c x^2
    {
        float s = 0.f;
        #pragma unroll
        for (int c = 0; c < C_DIM; c++) { float w = wTh[c * WROW2 + tid]; s = fmaf(w, w, s); }
        wnorm[tid] = s;
    }
    if (tid < TM) {
        float s = 0.f;
        #pragma unroll
        for (int c = 0; c < C_DIM; c++) { float x = xsd[(c * 64 + tid) * 2]; s = fmaf(x, x, s); }
        xnorm[tid] = s;
    }
    __syncthreads();

    // 8 warps: warp = rowg (rows rowg*8..+7); each warp covers all 256 local codes
    // k_local = 2*lane + 64*jj (+{0,1}), jj=0..3 -> conflict-free LDS.64
    const int rowg = tid >> 5;
    const int lane = tid & 31;

    unsigned long long acc[8][4];
    #pragma unroll
    for (int r = 0; r < 8; r++)
        #pragma unroll
        for (int j = 0; j < 4; j++) acc[r][j] = 0ULL;

    const ulonglong2* arow  = (const ulonglong2*)(xsd + rowg * 8 * 2);
    const unsigned long long* bbase = (const unsigned long long*)wTh + lane;

    #pragma unroll 4
    for (int c = 0; c < C_DIM; c++) {
        // 8 pre-duplicated row broadcasts via 4 LDS.128 (no MOV packing)
        unsigned long long aa[8];
        #pragma unroll
        for (int i = 0; i < 4; i++) {
            ulonglong2 v = arow[c * 32 + i];   // 64 floats per c = 32 ull = 16 ull2
            aa[2 * i]     = v.x;
            aa[2 * i + 1] = v.y;
        }
        // 4 code pairs (lane stride 8B -> conflict-free)
        const unsigned long long* bp = bbase + (size_t)c * (WROW2 / 2);
        unsigned long long bb[4];
        #pragma unroll
        for (int j = 0; j < 4; j++) bb[j] = bp[32 * j];
        #pragma unroll
        for (int r = 0; r < 8; r++) {
            #pragma unroll
            for (int j = 0; j < 4; j++) fma2(acc[r][j], aa[r], bb[j]);
        }
    }

    // epilogue: distances (reference rounding), per-warp argmin over this half
    const float INF = __int_as_float(0x7f800000);
    #pragma unroll
    for (int r = 0; r < 8; r++) {
        const int row = rowg * 8 + r;
        const int n   = n0 + row;
        const float xn = xnorm[row];

        float best = INF; int bidx = 0;
        float* dptr = out + DIST_OFF + (size_t)n * K_CB + half * KH + 2 * lane;
        #pragma unroll
        for (int j = 0; j < 4; j++) {
            float zlo, zhi; unpack2(acc[r][j], zlo, zhi);
            const int kl = 2 * lane + 64 * j;
            float dlo = (xn + wnorm[kl])     - 2.0f * zlo;
            float dhi = (xn + wnorm[kl + 1]) - 2.0f * zhi;
            dptr[64 * j]     = dlo;
            dptr[64 * j + 1] = dhi;
            if (dlo < best) { best = dlo; bidx = kl; }      // ascending k, strict '<'
            if (dhi < best) { best = dhi; bidx = kl + 1; }  // -> lowest index on ties
        }
        #pragma unroll
        for (int off = 16; off > 0; off >>= 1) {
            float ob = __shfl_xor_sync(0xffffffffu, best, off);
            int   oi = __shfl_xor_sync(0xffffffffu, bidx, off);
            if (ob < best || (ob == best && oi < bidx)) { best = ob; bidx = oi; }
        }
        if (lane == 0) {
            g_cbest[half * N_TOT + n] = best;
            g_cidx [half * N_TOT + n] = half * KH + bidx;
        }
    }
}

// ---------------- kernel B: combine halves, eidx, encodings, q_out, loss partials ----------------
extern "C" __global__ void __launch_bounds__(512, 2)
vq_emit(const float* __restrict__ inputs, const float* __restrict__ weight,
        float* __restrict__ out)
{
    __shared__ int   sm_idx[TM];
    __shared__ float red[512];

    const int tid = threadIdx.x;
    const int rb  = blockIdx.x;       // row block: rows [rb*64, rb*64+64)
    const int n0  = rb * TM;
    const int b   = n0 >> 10;
    const int p0  = n0 & (HW - 1);

    if (tid < TM) {
        const int n = n0 + tid;
        float b0 = g_cbest[n],         b1 = g_cbest[N_TOT + n];
        int   i0 = g_cidx[n],          i1 = g_cidx[N_TOT + n];
        int bi = (b1 < b0) ? i1 : i0;           // tie -> half 0 (lower index)
        sm_idx[tid] = bi;
        out[EIDX_OFF + (size_t)n] = (float)bi;
        atomicAdd(&g_hist[bi], 1);              // deterministic int atomic
    }
    __syncthreads();

    // encodings: one-hot rows (scalar stores: ENC_OFF is odd -> 4B alignment only)
    {
        float* ebase = out + ENC_OFF + (size_t)n0 * K_CB;
        #pragma unroll 8
        for (int i = tid; i < TM * K_CB; i += 512) {
            int row = i >> 9, k = i & 511;
            ebase[i] = (k == sm_idx[row]) ? 1.0f : 0.0f;
        }
    }

    // q_out tile (NCHW) with straight-through rounding; fused loss partial
    const float* xbase = inputs + (size_t)b * (C_DIM * HW) + p0;
    float* qbase = out + (size_t)b * (C_DIM * HW) + p0;
    float s = 0.f;
    #pragma unroll 2
    for (int i = tid; i < C_DIM * TM; i += 512) {
        int c = i >> 6, p = i & 63;
        float x = xbase[(size_t)c * HW + p];
        float q = weight[sm_idx[p] * C_DIM + c];  // L2-resident gather
        float d = q - x;
        qbase[(size_t)c * HW + p] = x + d;
        s = fmaf(d, d, s);
    }
    red[tid] = s;
    __syncthreads();
    #pragma unroll
    for (int off = 256; off > 0; off >>= 1) {
        if (tid < off) red[tid] += red[tid + off];
        __syncthreads();
    }
    if (tid == 0) g_lpart[rb] = red[0];
}

// ---------------- kernel C: loss + perplexity; re-zero hist ----------------
extern "C" __global__ void vq_finish(float* __restrict__ out)
{
    __shared__ float red[K_CB];
    const int tid = threadIdx.x;

    if (tid < B_DIM) {
        float s = 0.f;
        #pragma unroll
        for (int j = 0; j < 16; j++) s += g_lpart[tid * 16 + j];   // fixed order
        out[LOSS_OFF + tid] = 1.25f * (s * (1.0f / 65536.0f));
    }

    int h = g_hist[tid];
    g_hist[tid] = 0;                            // restore zero-at-entry invariant
    float p = (float)h * (1.0f / 65536.0f);
    red[tid] = -p * logf(p + 1e-10f);
    __syncthreads();
    #pragma unroll
    for (int off = 256; off > 0; off >>= 1) {
        if (tid < off) red[tid] += red[tid + off];
        __syncthreads();
    }
    if (tid == 0) out[PERP_OFF] = expf(red[0]);
}

// ---------------- launch ----------------
extern "C" void kernel_launch(void* const* d_in, const int* in_sizes, int n_in,
                              void* d_out, int out_size)
{
    const float* inputs = (const float*)d_in[0];
    const float* weight = (const float*)d_in[1];
    float* out = (float*)d_out;

    if (out_size != OUT_TOTAL) return;

    cudaFuncSetAttribute(vq_dist, cudaFuncAttributeMaxDynamicSharedMemorySize, SMEM_A);

    vq_dist  <<<(N_TOT / TM) * 2, ATHREADS, SMEM_A>>>(inputs, weight, out);
    vq_emit  <<<N_TOT / TM, 512>>>(inputs, weight, out);
    vq_finish<<<1, K_CB>>>(out);
}